// round 11
// baseline (speedup 1.0000x reference)
#include <cuda_runtime.h>
#include <cuda_fp16.h>
#include <cstdint>

#define NN 6144
#define NF 256
#define NH 4
#define ND 64
#define IB 128               // i-rows per CTA
#define JSP 3                // j splits
#define JL 2048              // j per CTA
#define NC2 32               // chunks of 64

// ---- scratch ----
__device__ __align__(256) __half  g_ht16[NH*NN*ND];   // [h][n][d]
__device__ __align__(256) __half2 g_srcAC2[NH*NN];    // (e^src, e^{0.2src})
__device__ __align__(256) __half2 g_tgtBD2[NH*NN];    // (e^tgt, e^{0.2tgt})
__device__ __align__(256) float   g_num[JSP*NH*NN*ND];
__device__ __align__(256) float   g_den[JSP*NH*NN];

// k3 smem byte offsets
#define POFF(b,h)  (((b)*4+(h))*16384)                 // 128 rows x 128B, swizzled
#define BOFF(b,h)  (131072 + ((b)*4+(h))*8192)         // 64 rows x 128B, swizzled
#define TOFF(s,h)  (196608 + ((s)*4+(h))*256)          // 64 half2
#define SMEM3      200704

__device__ __forceinline__ unsigned smem_u32(const void* p){
    return (unsigned)__cvta_generic_to_shared(p);
}
__device__ __forceinline__ unsigned h2u(__half2 v){ return *reinterpret_cast<unsigned*>(&v); }
__device__ __forceinline__ __half2 u2h(unsigned v){ return *reinterpret_cast<__half2*>(&v); }

// ------------------------------------------------------------------
// k1h: ht = h @ W via fp16 mma (fp32 accum) + fused src/tgt exps.
// grid (4 heads, 48), block 256.
// ------------------------------------------------------------------
#define HS_ST 264   // halves per row (256+8)
#define WS_ST 72    // halves per row (64+8)
#define SMEM1 ((128*HS_ST + 256*WS_ST)*2)

__global__ void __launch_bounds__(256) k1h_gemm(const float* __restrict__ h,
                                                const float* __restrict__ W,
                                                const float* __restrict__ a) {
    extern __shared__ char smem[];
    __half* Hs = reinterpret_cast<__half*>(smem);            // [128][HS_ST]
    __half* Ws = Hs + 128*HS_ST;                             // [256][WS_ST]
    const int tid = threadIdx.x, w = tid >> 5, lane = tid & 31;
    const int head = blockIdx.x;
    const int n0 = blockIdx.y * 128;

    {   // load h rows (convert fp32->fp16)
        int row = tid >> 1, ch = (tid & 1) * 128;
        #pragma unroll 8
        for (int q = 0; q < 32; q++){
            float4 v = *reinterpret_cast<const float4*>(&h[(size_t)(n0+row)*NF + ch + q*4]);
            __half2 lo = __floats2half2_rn(v.x, v.y), hi = __floats2half2_rn(v.z, v.w);
            uint2 o; o.x = h2u(lo); o.y = h2u(hi);
            *reinterpret_cast<uint2*>(&Hs[row*HS_ST + ch + q*4]) = o;
        }
    }
    {   // load W column block for this head
        int k = tid;
        #pragma unroll 4
        for (int q = 0; q < 16; q++){
            float4 v = *reinterpret_cast<const float4*>(&W[(size_t)k*NF + head*ND + q*4]);
            __half2 lo = __floats2half2_rn(v.x, v.y), hi = __floats2half2_rn(v.z, v.w);
            uint2 o; o.x = h2u(lo); o.y = h2u(hi);
            *reinterpret_cast<uint2*>(&Ws[k*WS_ST + q*4]) = o;
        }
    }
    __syncthreads();

    float acc[8][4] = {};
    #pragma unroll
    for (int ks = 0; ks < 16; ks++){
        uint32_t af[4];
        {
            int r = w*16 + (lane & 15);
            unsigned addr = smem_u32(Hs) + (unsigned)(r*HS_ST*2 + ks*32 + (lane>>4)*16);
            asm volatile("ldmatrix.sync.aligned.m8n8.x4.shared.b16 {%0,%1,%2,%3}, [%4];\n"
                : "=r"(af[0]),"=r"(af[1]),"=r"(af[2]),"=r"(af[3]) : "r"(addr));
        }
        uint32_t bf[8][2];
        #pragma unroll
        for (int nt = 0; nt < 8; nt++){
            int kr = ks*16 + (lane & 15);
            unsigned addr = smem_u32(Ws) + (unsigned)(kr*WS_ST*2 + nt*16);
            asm volatile("ldmatrix.sync.aligned.m8n8.x2.trans.shared.b16 {%0,%1}, [%2];\n"
                : "=r"(bf[nt][0]),"=r"(bf[nt][1]) : "r"(addr));
        }
        #pragma unroll
        for (int nt = 0; nt < 8; nt++)
            asm volatile(
              "mma.sync.aligned.m16n8k16.row.col.f32.f16.f16.f32 "
              "{%0,%1,%2,%3}, {%4,%5,%6,%7}, {%8,%9}, {%0,%1,%2,%3};\n"
              : "+f"(acc[nt][0]),"+f"(acc[nt][1]),"+f"(acc[nt][2]),"+f"(acc[nt][3])
              : "r"(af[0]),"r"(af[1]),"r"(af[2]),"r"(af[3]),
                "r"(bf[nt][0]),"r"(bf[nt][1]));
    }

    int r0 = n0 + w*16 + (lane >> 2);
    #pragma unroll
    for (int nt = 0; nt < 8; nt++){
        int d = nt*8 + (lane & 3)*2;
        *reinterpret_cast<__half2*>(&g_ht16[((size_t)head*NN + r0)*ND + d])
            = __floats2half2_rn(acc[nt][0], acc[nt][1]);
        *reinterpret_cast<__half2*>(&g_ht16[((size_t)head*NN + r0 + 8)*ND + d])
            = __floats2half2_rn(acc[nt][2], acc[nt][3]);
    }

    // ---- fused src/tgt logits (fp32) ----
    float s0=0.f, s1=0.f, t0=0.f, t1=0.f;
    #pragma unroll
    for (int nt = 0; nt < 8; nt++){
        int d = nt*8 + (lane & 3)*2;
        float2 av = *reinterpret_cast<const float2*>(&a[head*2*ND + d]);
        float2 bv = *reinterpret_cast<const float2*>(&a[head*2*ND + ND + d]);
        s0 += acc[nt][0]*av.x + acc[nt][1]*av.y;
        t0 += acc[nt][0]*bv.x + acc[nt][1]*bv.y;
        s1 += acc[nt][2]*av.x + acc[nt][3]*av.y;
        t1 += acc[nt][2]*bv.x + acc[nt][3]*bv.y;
    }
    #pragma unroll
    for (int off = 1; off <= 2; off <<= 1){
        s0 += __shfl_xor_sync(0xffffffffu, s0, off);
        s1 += __shfl_xor_sync(0xffffffffu, s1, off);
        t0 += __shfl_xor_sync(0xffffffffu, t0, off);
        t1 += __shfl_xor_sync(0xffffffffu, t1, off);
    }
    if ((lane & 3) == 0){
        g_srcAC2[head*NN + r0]     = __floats2half2_rn(expf(s0), expf(0.2f*s0));
        g_srcAC2[head*NN + r0 + 8] = __floats2half2_rn(expf(s1), expf(0.2f*s1));
        g_tgtBD2[head*NN + r0]     = __floats2half2_rn(expf(t0), expf(0.2f*t0));
        g_tgtBD2[head*NN + r0 + 8] = __floats2half2_rn(expf(t1), expf(0.2f*t1));
    }
}

// ------------------------------------------------------------------
// k3: flash GAT, 144 CTAs (48 ib x 3 split), 256 threads / 8 warps.
// warp w: head = w&3, m-half = w>>2. Per chunk: 4 k-step MMAs with one
// head's P-gen (next chunk) interleaved after each k-step.
// ------------------------------------------------------------------
__global__ void __launch_bounds__(256, 1) k3_gat(const int* __restrict__ adj){
    extern __shared__ char smem[];
    const unsigned sbase = smem_u32(smem);
    const int tid = threadIdx.x, w = tid >> 5, lane = tid & 31;
    const int h = w & 3, mh = w >> 2;
    const int ib = blockIdx.x / 3, split = blockIdx.x % 3;
    const int i0 = ib * IB, j0 = split * JL;
    const int rg = tid >> 2, jg = tid & 3;    // rows 2rg,2rg+1 ; j block jg*16

    __half2 AC[2][NH];
    #pragma unroll
    for (int rr = 0; rr < 2; rr++)
        #pragma unroll
        for (int hh = 0; hh < NH; hh++)
            AC[rr][hh] = g_srcAC2[hh*NN + i0 + 2*rg + rr];

    float den[2][NH] = {};
    float acc[4][8][4] = {};     // [mt][nt][frag]

    auto loadB = [&](int buf, int c){
        #pragma unroll
        for (int t = 0; t < 8; t++){
            int idx = tid + t*256;
            int hh = idx >> 9, rw = (idx >> 3) & 63, s = idx & 7;
            const __half* src = &g_ht16[((size_t)hh*NN + j0 + c*64 + rw)*ND + s*8];
            unsigned dst = sbase + BOFF(buf,hh) + rw*128 + ((s*16) ^ ((rw&7)<<4));
            asm volatile("cp.async.cg.shared.global [%0], [%1], 16;\n" :: "r"(dst), "l"(src));
        }
    };
    auto loadTgt = [&](int slot, int c){
        if (tid < 64){
            int hh = tid >> 4, q = tid & 15;
            const __half2* src = g_tgtBD2 + hh*NN + j0 + c*64 + q*4;
            unsigned dst = sbase + TOFF(slot,hh) + q*16;
            asm volatile("cp.async.cg.shared.global [%0], [%1], 16;\n" :: "r"(dst), "l"(src));
        }
    };
    auto loadAdj = [&](int4* dst, int cc){
        #pragma unroll
        for (int rr = 0; rr < 2; rr++){
            const int4* base = reinterpret_cast<const int4*>(
                adj + (size_t)(i0 + 2*rg + rr)*NN + j0 + cc*64 + jg*16);
            #pragma unroll
            for (int q = 0; q < 4; q++) dst[rr*4+q] = __ldcs(base + q);
        }
    };
    auto buildMk = [&](unsigned (*mk)[8], const int4* adjr){
        #pragma unroll
        for (int rr = 0; rr < 2; rr++)
            #pragma unroll
            for (int p = 0; p < 8; p++){
                int4 aq = adjr[rr*4 + (p>>1)];
                int a0 = (p&1) ? aq.z : aq.x;
                int a1 = (p&1) ? aq.w : aq.y;
                mk[rr][p] = (unsigned)a0*0x3C00u + (unsigned)a1*0x3C000000u;
            }
    };

    auto pgen_head = [&](int buf, int slot, const unsigned (*mk)[8], int hh){
        const uint4* tp = reinterpret_cast<const uint4*>(smem + TOFF(slot,hh) + jg*64);
        uint4 T0 = tp[0], T1 = tp[1], T2 = tp[2], T3 = tp[3];
        unsigned tv[16] = {T0.x,T0.y,T0.z,T0.w, T1.x,T1.y,T1.z,T1.w,
                           T2.x,T2.y,T2.z,T2.w, T3.x,T3.y,T3.z,T3.w};
        #pragma unroll
        for (int rr = 0; rr < 2; rr++){
            const int r = 2*rg + rr;
            __half2 ac = AC[rr][hh];
            unsigned o[8];
            float dsum = 0.f;
            #pragma unroll
            for (int p = 0; p < 8; p++){
                __half2 t0 = __hmul2(ac, u2h(tv[2*p]));
                __half2 t1 = __hmul2(ac, u2h(tv[2*p+1]));
                __half p0 = __hmax(__low2half(t0), __high2half(t0));
                __half p1 = __hmax(__low2half(t1), __high2half(t1));
                __half2 pm = __hmul2(__halves2half2(p0, p1), u2h(mk[rr][p]));
                o[p] = h2u(pm);
                float2 f = __half22float2(pm);
                dsum += f.x + f.y;
            }
            den[rr][hh] += dsum;
            unsigned sw = (unsigned)((r&7)<<4);
            char* pb = smem + POFF(buf,hh) + r*128;
            uint4 o0; o0.x=o[0]; o0.y=o[1]; o0.z=o[2]; o0.w=o[3];
            uint4 o1; o1.x=o[4]; o1.y=o[5]; o1.z=o[6]; o1.w=o[7];
            *reinterpret_cast<uint4*>(pb + (((unsigned)(jg*32))      ^ sw)) = o0;
            *reinterpret_cast<uint4*>(pb + (((unsigned)(jg*32 + 16)) ^ sw)) = o1;
        }
    };

    auto mma_ks = [&](int buf, int ks){
        const unsigned PB = sbase + POFF(buf,h);
        const unsigned BB = sbase + BOFF(buf,h);
        uint32_t af[4][4];
        #pragma unroll
        for (int mt = 0; mt < 4; mt++){
            int r = mh*64 + mt*16 + (lane & 15);
            unsigned cb = (unsigned)(ks*32 + (lane>>4)*16);
            unsigned addr = PB + r*128 + (cb ^ ((r&7)<<4));
            asm volatile("ldmatrix.sync.aligned.m8n8.x4.shared.b16 {%0,%1,%2,%3}, [%4];\n"
                : "=r"(af[mt][0]),"=r"(af[mt][1]),"=r"(af[mt][2]),"=r"(af[mt][3])
                : "r"(addr));
        }
        uint32_t bf[8][2];
        #pragma unroll
        for (int nt = 0; nt < 8; nt++){
            int jr = ks*16 + (lane & 15);
            unsigned addr = BB + jr*128 + (((unsigned)(nt*16)) ^ ((jr&7)<<4));
            asm volatile("ldmatrix.sync.aligned.m8n8.x2.trans.shared.b16 {%0,%1}, [%2];\n"
                : "=r"(bf[nt][0]),"=r"(bf[nt][1]) : "r"(addr));
        }
        #pragma unroll
        for (int mt = 0; mt < 4; mt++)
            #pragma unroll
            for (int nt = 0; nt < 8; nt++)
                asm volatile(
                  "mma.sync.aligned.m16n8k16.row.col.f32.f16.f16.f32 "
                  "{%0,%1,%2,%3}, {%4,%5,%6,%7}, {%8,%9}, {%0,%1,%2,%3};\n"
                  : "+f"(acc[mt][nt][0]),"+f"(acc[mt][nt][1]),
                    "+f"(acc[mt][nt][2]),"+f"(acc[mt][nt][3])
                  : "r"(af[mt][0]),"r"(af[mt][1]),"r"(af[mt][2]),"r"(af[mt][3]),
                    "r"(bf[nt][0]),"r"(bf[nt][1]));
    };

    // ---- prologue ----
    int4 adjr[8];
    loadTgt(0, 0); loadTgt(1, 1); loadB(0, 0);
    asm volatile("cp.async.commit_group;\n" ::: "memory");
    loadAdj(adjr, 0);
    asm volatile("cp.async.wait_group 0;\n" ::: "memory");
    __syncthreads();
    {
        unsigned mk[2][8];
        buildMk(mk, adjr);
        #pragma unroll
        for (int hh = 0; hh < NH; hh++) pgen_head(0, 0, mk, hh);   // P(0)
    }

    // ---- main loop: mma k-steps interleaved with next-chunk pgen ----
    for (int c = 0; c < NC2; ++c){
        const int buf = c & 1, nb = buf ^ 1;
        const int slot = (c + 1) & 3;
        const bool more = (c + 1 < NC2);
        asm volatile("cp.async.wait_group 0;\n" ::: "memory");  // B(c), tgt(c+1) landed
        __syncthreads();                                        // + P(c) visible
        if (more) loadB(nb, c + 1);
        if (c + 2 < NC2) loadTgt((c + 2) & 3, c + 2);
        asm volatile("cp.async.commit_group;\n" ::: "memory");
        if (more) loadAdj(adjr, c + 1);          // lands under first k-steps

        unsigned mk[2][8];
        mma_ks(buf, 0);
        if (more){ buildMk(mk, adjr); pgen_head(nb, slot, mk, 0); }
        mma_ks(buf, 1);
        if (more) pgen_head(nb, slot, mk, 1);
        mma_ks(buf, 2);
        if (more) pgen_head(nb, slot, mk, 2);
        mma_ks(buf, 3);
        if (more) pgen_head(nb, slot, mk, 3);
    }

    // ---- epilogue: den lane-reduce + partial writes ----
    #pragma unroll
    for (int rr = 0; rr < 2; rr++)
        #pragma unroll
        for (int hh = 0; hh < NH; hh++){
            float v = den[rr][hh];
            v += __shfl_xor_sync(0xffffffffu, v, 1);
            v += __shfl_xor_sync(0xffffffffu, v, 2);
            if (jg == 0)
                g_den[((size_t)split*NH + hh)*NN + i0 + 2*rg + rr] = v;
        }
    #pragma unroll
    for (int mt = 0; mt < 4; mt++){
        int r0 = i0 + mh*64 + mt*16 + (lane >> 2);
        #pragma unroll
        for (int nt = 0; nt < 8; nt++){
            int d = nt*8 + (lane & 3)*2;
            float2 v0; v0.x = acc[mt][nt][0]; v0.y = acc[mt][nt][1];
            float2 v1; v1.x = acc[mt][nt][2]; v1.y = acc[mt][nt][3];
            *reinterpret_cast<float2*>(&g_num[(((size_t)split*NH + h)*NN + r0)*ND + d]) = v0;
            *reinterpret_cast<float2*>(&g_num[(((size_t)split*NH + h)*NN + r0 + 8)*ND + d]) = v1;
        }
    }
}

// ------------------------------------------------------------------
// k4: combine split partials, divide, mean over heads.
// grid NN/16, block 256: 16 rows/CTA, 16 threads x float4 per row.
// ------------------------------------------------------------------
__global__ void __launch_bounds__(256) k4_reduce(float* __restrict__ out){
    const int tid = threadIdx.x;
    const int i  = blockIdx.x * 16 + (tid >> 4);
    const int d4 = (tid & 15) * 4;
    __shared__ float rinv[16][NH];
    if (tid < 64){
        int row = blockIdx.x * 16 + (tid >> 2), hh = tid & 3;
        float s = 0.f;
        #pragma unroll
        for (int sp = 0; sp < JSP; sp++) s += g_den[((size_t)sp*NH + hh)*NN + row];
        rinv[tid >> 2][hh] = 1.f / s;
    }
    __syncthreads();
    float4 accv = make_float4(0.f, 0.f, 0.f, 0.f);
    #pragma unroll
    for (int hh = 0; hh < NH; hh++){
        float4 s = make_float4(0.f, 0.f, 0.f, 0.f);
        #pragma unroll
        for (int sp = 0; sp < JSP; sp++){
            float4 v = *reinterpret_cast<const float4*>(
                &g_num[(((size_t)sp*NH + hh)*NN + i)*ND + d4]);
            s.x += v.x; s.y += v.y; s.z += v.z; s.w += v.w;
        }
        float r = rinv[tid >> 4][hh];
        accv.x += s.x*r; accv.y += s.y*r; accv.z += s.z*r; accv.w += s.w*r;
    }
    accv.x *= 0.25f; accv.y *= 0.25f; accv.z *= 0.25f; accv.w *= 0.25f;
    *reinterpret_cast<float4*>(&out[(size_t)i*ND + d4]) = accv;
}

// ------------------------------------------------------------------
extern "C" void kernel_launch(void* const* d_in, const int* in_sizes, int n_in,
                              void* d_out, int out_size) {
    const float* h   = (const float*)d_in[0];
    const int*   adj = (const int*)d_in[1];
    const float* W   = (const float*)d_in[2];
    const float* a   = (const float*)d_in[3];
    float* out = (float*)d_out;

    cudaFuncSetAttribute(k1h_gemm, cudaFuncAttributeMaxDynamicSharedMemorySize, SMEM1);
    cudaFuncSetAttribute(k3_gat,  cudaFuncAttributeMaxDynamicSharedMemorySize, SMEM3);

    k1h_gemm<<<dim3(4, 48), 256, SMEM1>>>(h, W, a);
    k3_gat<<<48*JSP, 256, SMEM3>>>(adj);
    k4_reduce<<<NN/16, 256>>>(out);
}

// round 13
// speedup vs baseline: 1.0199x; 1.0199x over previous
#include <cuda_runtime.h>
#include <cuda_fp16.h>
#include <cstdint>

#define NN 6144
#define NF 256
#define NH 4
#define ND 64
#define IB 128               // i-rows per CTA
#define JSP 3                // j splits
#define JL 2048              // j per CTA
#define NC2 32               // chunks of 64

// ---- scratch ----
__device__ __align__(256) __half  g_ht16[NH*NN*ND];   // [h][n][d]
__device__ __align__(256) __half2 g_srcAC2[NH*NN];    // (e^src, e^{0.2src})
__device__ __align__(256) __half2 g_tgtBD2[NH*NN];    // (e^tgt, e^{0.2tgt})
__device__ __align__(256) float   g_num[JSP*NH*NN*ND];
__device__ __align__(256) float   g_den[JSP*NH*NN];

// k3 smem byte offsets
#define POFF(b,h)  (((b)*4+(h))*16384)                 // 128 rows x 128B, swizzled
#define BOFF(b,h)  (131072 + ((b)*4+(h))*8192)         // 64 rows x 128B, swizzled
#define TOFF(s,h)  (196608 + ((s)*4+(h))*256)          // 64 half2
#define SMEM3      200704

__device__ __forceinline__ unsigned smem_u32(const void* p){
    return (unsigned)__cvta_generic_to_shared(p);
}
__device__ __forceinline__ unsigned h2u(__half2 v){ return *reinterpret_cast<unsigned*>(&v); }
__device__ __forceinline__ __half2 u2h(unsigned v){ return *reinterpret_cast<__half2*>(&v); }

// ------------------------------------------------------------------
// k1h: ht = h @ W via fp16 mma (fp32 accum) + fused src/tgt exps.
// grid (4 heads, 48), block 256.
// ------------------------------------------------------------------
#define HS_ST 264   // halves per row (256+8)
#define WS_ST 72    // halves per row (64+8)
#define SMEM1 ((128*HS_ST + 256*WS_ST)*2)

__global__ void __launch_bounds__(256) k1h_gemm(const float* __restrict__ h,
                                                const float* __restrict__ W,
                                                const float* __restrict__ a) {
    extern __shared__ char smem[];
    __half* Hs = reinterpret_cast<__half*>(smem);            // [128][HS_ST]
    __half* Ws = Hs + 128*HS_ST;                             // [256][WS_ST]
    const int tid = threadIdx.x, w = tid >> 5, lane = tid & 31;
    const int head = blockIdx.x;
    const int n0 = blockIdx.y * 128;

    {   // load h rows (convert fp32->fp16)
        int row = tid >> 1, ch = (tid & 1) * 128;
        #pragma unroll 8
        for (int q = 0; q < 32; q++){
            float4 v = *reinterpret_cast<const float4*>(&h[(size_t)(n0+row)*NF + ch + q*4]);
            __half2 lo = __floats2half2_rn(v.x, v.y), hi = __floats2half2_rn(v.z, v.w);
            uint2 o; o.x = h2u(lo); o.y = h2u(hi);
            *reinterpret_cast<uint2*>(&Hs[row*HS_ST + ch + q*4]) = o;
        }
    }
    {   // load W column block for this head
        int k = tid;
        #pragma unroll 4
        for (int q = 0; q < 16; q++){
            float4 v = *reinterpret_cast<const float4*>(&W[(size_t)k*NF + head*ND + q*4]);
            __half2 lo = __floats2half2_rn(v.x, v.y), hi = __floats2half2_rn(v.z, v.w);
            uint2 o; o.x = h2u(lo); o.y = h2u(hi);
            *reinterpret_cast<uint2*>(&Ws[k*WS_ST + q*4]) = o;
        }
    }
    __syncthreads();

    float acc[8][4] = {};
    #pragma unroll
    for (int ks = 0; ks < 16; ks++){
        uint32_t af[4];
        {
            int r = w*16 + (lane & 15);
            unsigned addr = smem_u32(Hs) + (unsigned)(r*HS_ST*2 + ks*32 + (lane>>4)*16);
            asm volatile("ldmatrix.sync.aligned.m8n8.x4.shared.b16 {%0,%1,%2,%3}, [%4];\n"
                : "=r"(af[0]),"=r"(af[1]),"=r"(af[2]),"=r"(af[3]) : "r"(addr));
        }
        uint32_t bf[8][2];
        #pragma unroll
        for (int nt = 0; nt < 8; nt++){
            int kr = ks*16 + (lane & 15);
            unsigned addr = smem_u32(Ws) + (unsigned)(kr*WS_ST*2 + nt*16);
            asm volatile("ldmatrix.sync.aligned.m8n8.x2.trans.shared.b16 {%0,%1}, [%2];\n"
                : "=r"(bf[nt][0]),"=r"(bf[nt][1]) : "r"(addr));
        }
        #pragma unroll
        for (int nt = 0; nt < 8; nt++)
            asm volatile(
              "mma.sync.aligned.m16n8k16.row.col.f32.f16.f16.f32 "
              "{%0,%1,%2,%3}, {%4,%5,%6,%7}, {%8,%9}, {%0,%1,%2,%3};\n"
              : "+f"(acc[nt][0]),"+f"(acc[nt][1]),"+f"(acc[nt][2]),"+f"(acc[nt][3])
              : "r"(af[0]),"r"(af[1]),"r"(af[2]),"r"(af[3]),
                "r"(bf[nt][0]),"r"(bf[nt][1]));
    }

    int r0 = n0 + w*16 + (lane >> 2);
    #pragma unroll
    for (int nt = 0; nt < 8; nt++){
        int d = nt*8 + (lane & 3)*2;
        *reinterpret_cast<__half2*>(&g_ht16[((size_t)head*NN + r0)*ND + d])
            = __floats2half2_rn(acc[nt][0], acc[nt][1]);
        *reinterpret_cast<__half2*>(&g_ht16[((size_t)head*NN + r0 + 8)*ND + d])
            = __floats2half2_rn(acc[nt][2], acc[nt][3]);
    }

    // ---- fused src/tgt logits (fp32) ----
    float s0=0.f, s1=0.f, t0=0.f, t1=0.f;
    #pragma unroll
    for (int nt = 0; nt < 8; nt++){
        int d = nt*8 + (lane & 3)*2;
        float2 av = *reinterpret_cast<const float2*>(&a[head*2*ND + d]);
        float2 bv = *reinterpret_cast<const float2*>(&a[head*2*ND + ND + d]);
        s0 += acc[nt][0]*av.x + acc[nt][1]*av.y;
        t0 += acc[nt][0]*bv.x + acc[nt][1]*bv.y;
        s1 += acc[nt][2]*av.x + acc[nt][3]*av.y;
        t1 += acc[nt][2]*bv.x + acc[nt][3]*bv.y;
    }
    #pragma unroll
    for (int off = 1; off <= 2; off <<= 1){
        s0 += __shfl_xor_sync(0xffffffffu, s0, off);
        s1 += __shfl_xor_sync(0xffffffffu, s1, off);
        t0 += __shfl_xor_sync(0xffffffffu, t0, off);
        t1 += __shfl_xor_sync(0xffffffffu, t1, off);
    }
    if ((lane & 3) == 0){
        g_srcAC2[head*NN + r0]     = __floats2half2_rn(expf(s0), expf(0.2f*s0));
        g_srcAC2[head*NN + r0 + 8] = __floats2half2_rn(expf(s1), expf(0.2f*s1));
        g_tgtBD2[head*NN + r0]     = __floats2half2_rn(expf(t0), expf(0.2f*t0));
        g_tgtBD2[head*NN + r0 + 8] = __floats2half2_rn(expf(t1), expf(0.2f*t1));
    }
}

// ------------------------------------------------------------------
// k3: warp-specialized flash GAT. 144 CTAs, 384 threads / 12 warps.
// warps 0-7: MMA consumers (head = w&3, m-half = w>>2)
// warps 8-11: producers (staging + P-gen + denominator)
// ------------------------------------------------------------------
__global__ void __launch_bounds__(384, 1) k3_gat(const int* __restrict__ adj){
    extern __shared__ char smem[];
    const unsigned sbase = smem_u32(smem);
    const int tid = threadIdx.x, w = tid >> 5, lane = tid & 31;
    const int ib = blockIdx.x / 3, split = blockIdx.x % 3;
    const int i0 = ib * IB, j0 = split * JL;

    if (w >= 8){
        // ================= producers (128 threads) =================
        const int pt = tid - 256;
        const int rp = pt >> 1, jh = pt & 1;     // rows 2rp,2rp+1 ; j-half jh*32

        __half2 AC[2][NH];
        #pragma unroll
        for (int rr = 0; rr < 2; rr++)
            #pragma unroll
            for (int hh = 0; hh < NH; hh++)
                AC[rr][hh] = g_srcAC2[hh*NN + i0 + 2*rp + rr];

        float den[2][NH] = {};
        int4 raw[16];
        unsigned mk[2][16];

        auto loadB = [&](int buf, int c){
            #pragma unroll
            for (int t = 0; t < 16; t++){
                int idx = pt + t*128;
                int hh = idx >> 9, rw = (idx >> 3) & 63, s = idx & 7;
                const __half* src = &g_ht16[((size_t)hh*NN + j0 + c*64 + rw)*ND + s*8];
                unsigned dst = sbase + BOFF(buf,hh) + rw*128 + ((s*16) ^ ((rw&7)<<4));
                asm volatile("cp.async.cg.shared.global [%0], [%1], 16;\n" :: "r"(dst), "l"(src));
            }
        };
        auto loadTgt = [&](int slot, int c){
            if (pt < 64){
                int hh = pt >> 4, q = pt & 15;
                const __half2* src = g_tgtBD2 + hh*NN + j0 + c*64 + q*4;
                unsigned dst = sbase + TOFF(slot,hh) + q*16;
                asm volatile("cp.async.cg.shared.global [%0], [%1], 16;\n" :: "r"(dst), "l"(src));
            }
        };
        auto loadRaw = [&](int c){
            #pragma unroll
            for (int rr = 0; rr < 2; rr++){
                const int4* base = reinterpret_cast<const int4*>(
                    adj + (size_t)(i0 + 2*rp + rr)*NN + j0 + c*64 + jh*32);
                #pragma unroll
                for (int q = 0; q < 8; q++) raw[rr*8+q] = __ldcs(base + q);
            }
        };
        auto buildMk = [&](){
            #pragma unroll
            for (int rr = 0; rr < 2; rr++)
                #pragma unroll
                for (int q = 0; q < 8; q++){
                    int4 v = raw[rr*8+q];
                    mk[rr][2*q]   = (unsigned)v.x*0x3C00u + (unsigned)v.y*0x3C000000u;
                    mk[rr][2*q+1] = (unsigned)v.z*0x3C00u + (unsigned)v.w*0x3C000000u;
                }
        };
        auto pgen = [&](int buf, int slot){
            #pragma unroll
            for (int hh = 0; hh < NH; hh++){
                #pragma unroll
                for (int q4 = 0; q4 < 2; q4++){   // 16 j per sub-batch
                    const uint4* tp = reinterpret_cast<const uint4*>(
                        smem + TOFF(slot,hh) + jh*128 + q4*64);
                    uint4 Ta = tp[0], Tb = tp[1], Tc = tp[2], Td = tp[3];
                    unsigned tv[16] = {Ta.x,Ta.y,Ta.z,Ta.w, Tb.x,Tb.y,Tb.z,Tb.w,
                                       Tc.x,Tc.y,Tc.z,Tc.w, Td.x,Td.y,Td.z,Td.w};
                    #pragma unroll
                    for (int rr = 0; rr < 2; rr++){
                        const int r = 2*rp + rr;
                        __half2 ac = AC[rr][hh];
                        unsigned o[8];
                        float dsum = 0.f;
                        #pragma unroll
                        for (int q = 0; q < 8; q++){
                            __half2 t0 = __hmul2(ac, u2h(tv[2*q]));
                            __half2 t1 = __hmul2(ac, u2h(tv[2*q+1]));
                            __half p0 = __hmax(__low2half(t0), __high2half(t0));
                            __half p1 = __hmax(__low2half(t1), __high2half(t1));
                            __half2 pm = __hmul2(__halves2half2(p0, p1), u2h(mk[rr][q4*8+q]));
                            o[q] = h2u(pm);
                            float2 f = __half22float2(pm);
                            dsum += f.x + f.y;
                        }
                        den[rr][hh] += dsum;
                        unsigned sw = (unsigned)((r&7)<<4);
                        char* pb = smem + POFF(buf,hh) + r*128;
                        uint4 o0; o0.x=o[0]; o0.y=o[1]; o0.z=o[2]; o0.w=o[3];
                        uint4 o1; o1.x=o[4]; o1.y=o[5]; o1.z=o[6]; o1.w=o[7];
                        *reinterpret_cast<uint4*>(pb + (((unsigned)(jh*64 + q4*32))      ^ sw)) = o0;
                        *reinterpret_cast<uint4*>(pb + (((unsigned)(jh*64 + q4*32 + 16)) ^ sw)) = o1;
                    }
                }
            }
        };

        // ---- prologue ----
        loadTgt(0, 0); loadTgt(1, 1); loadB(0, 0);
        asm volatile("cp.async.commit_group;\n" ::: "memory");
        loadRaw(0);
        asm volatile("cp.async.wait_group 0;\n" ::: "memory");
        buildMk();            // masks for chunk 0
        loadRaw(1);           // in flight during pgen(0)
        pgen(0, 0);           // P(0)
        __syncthreads();

        // ---- main loop ----
        for (int c = 0; c < NC2; ++c){
            const int nb = (c & 1) ^ 1;
            if (c + 1 < NC2) loadB(nb, c + 1);
            if (c + 2 < NC2) loadTgt((c + 2) & 3, c + 2);
            asm volatile("cp.async.commit_group;\n" ::: "memory");
            if (c + 1 < NC2){
                buildMk();                        // from raw(c+1)
                if (c + 2 < NC2) loadRaw(c + 2);  // lands during pgen
                pgen(nb, (c + 1) & 3);
            }
            asm volatile("cp.async.wait_group 0;\n" ::: "memory");
            __syncthreads();
        }

        // ---- den epilogue ----
        #pragma unroll
        for (int rr = 0; rr < 2; rr++)
            #pragma unroll
            for (int hh = 0; hh < NH; hh++){
                float v = den[rr][hh];
                v += __shfl_xor_sync(0xffffffffu, v, 1);
                if (jh == 0)
                    g_den[((size_t)split*NH + hh)*NN + i0 + 2*rp + rr] = v;
            }
    } else {
        // ================= consumers (8 warps) =================
        const int h = w & 3, mh = w >> 2;
        float acc[4][8][4] = {};     // [mt][nt][frag]

        __syncthreads();             // match producer prologue barrier

        for (int c = 0; c < NC2; ++c){
            const int buf = c & 1;
            const unsigned PB = sbase + POFF(buf,h);
            const unsigned BB = sbase + BOFF(buf,h);
            #pragma unroll
            for (int ks = 0; ks < 4; ks++){
                uint32_t bf[8][2];
                #pragma unroll
                for (int nt = 0; nt < 8; nt++){
                    int jr = ks*16 + (lane & 15);
                    unsigned addr = BB + jr*128 + (((unsigned)(nt*16)) ^ ((jr&7)<<4));
                    asm volatile("ldmatrix.sync.aligned.m8n8.x2.trans.shared.b16 {%0,%1}, [%2];\n"
                        : "=r"(bf[nt][0]),"=r"(bf[nt][1]) : "r"(addr));
                }
                #pragma unroll
                for (int mt = 0; mt < 4; mt++){
                    uint32_t af[4];
                    int r = mh*64 + mt*16 + (lane & 15);
                    unsigned cb = (unsigned)(ks*32 + (lane>>4)*16);
                    unsigned addr = PB + r*128 + (cb ^ ((r&7)<<4));
                    asm volatile("ldmatrix.sync.aligned.m8n8.x4.shared.b16 {%0,%1,%2,%3}, [%4];\n"
                        : "=r"(af[0]),"=r"(af[1]),"=r"(af[2]),"=r"(af[3]) : "r"(addr));
                    #pragma unroll
                    for (int nt = 0; nt < 8; nt++)
                        asm volatile(
                          "mma.sync.aligned.m16n8k16.row.col.f32.f16.f16.f32 "
                          "{%0,%1,%2,%3}, {%4,%5,%6,%7}, {%8,%9}, {%0,%1,%2,%3};\n"
                          : "+f"(acc[mt][nt][0]),"+f"(acc[mt][nt][1]),
                            "+f"(acc[mt][nt][2]),"+f"(acc[mt][nt][3])
                          : "r"(af[0]),"r"(af[1]),"r"(af[2]),"r"(af[3]),
                            "r"(bf[nt][0]),"r"(bf[nt][1]));
                }
            }
            __syncthreads();
        }

        // ---- numerator epilogue ----
        #pragma unroll
        for (int mt = 0; mt < 4; mt++){
            int r0 = i0 + mh*64 + mt*16 + (lane >> 2);
            #pragma unroll
            for (int nt = 0; nt < 8; nt++){
                int d = nt*8 + (lane & 3)*2;
                float2 v0; v0.x = acc[mt][nt][0]; v0.y = acc[mt][nt][1];
                float2 v1; v1.x = acc[mt][nt][2]; v1.y = acc[mt][nt][3];
                *reinterpret_cast<float2*>(&g_num[(((size_t)split*NH + h)*NN + r0)*ND + d]) = v0;
                *reinterpret_cast<float2*>(&g_num[(((size_t)split*NH + h)*NN + r0 + 8)*ND + d]) = v1;
            }
        }
    }
}

// ------------------------------------------------------------------
// k4: combine split partials, divide, mean over heads.
// grid NN/16, block 256: 16 rows/CTA, 16 threads x float4 per row.
// ------------------------------------------------------------------
__global__ void __launch_bounds__(256) k4_reduce(float* __restrict__ out){
    const int tid = threadIdx.x;
    const int i  = blockIdx.x * 16 + (tid >> 4);
    const int d4 = (tid & 15) * 4;
    __shared__ float rinv[16][NH];
    if (tid < 64){
        int row = blockIdx.x * 16 + (tid >> 2), hh = tid & 3;
        float s = 0.f;
        #pragma unroll
        for (int sp = 0; sp < JSP; sp++) s += g_den[((size_t)sp*NH + hh)*NN + row];
        rinv[tid >> 2][hh] = 1.f / s;
    }
    __syncthreads();
    float4 accv = make_float4(0.f, 0.f, 0.f, 0.f);
    #pragma unroll
    for (int hh = 0; hh < NH; hh++){
        float4 s = make_float4(0.f, 0.f, 0.f, 0.f);
        #pragma unroll
        for (int sp = 0; sp < JSP; sp++){
            float4 v = *reinterpret_cast<const float4*>(
                &g_num[(((size_t)sp*NH + hh)*NN + i)*ND + d4]);
            s.x += v.x; s.y += v.y; s.z += v.z; s.w += v.w;
        }
        float r = rinv[tid >> 4][hh];
        accv.x += s.x*r; accv.y += s.y*r; accv.z += s.z*r; accv.w += s.w*r;
    }
    accv.x *= 0.25f; accv.y *= 0.25f; accv.z *= 0.25f; accv.w *= 0.25f;
    *reinterpret_cast<float4*>(&out[(size_t)i*ND + d4]) = accv;
}

// ------------------------------------------------------------------
extern "C" void kernel_launch(void* const* d_in, const int* in_sizes, int n_in,
                              void* d_out, int out_size) {
    const float* h   = (const float*)d_in[0];
    const int*   adj = (const int*)d_in[1];
    const float* W   = (const float*)d_in[2];
    const float* a   = (const float*)d_in[3];
    float* out = (float*)d_out;

    cudaFuncSetAttribute(k1h_gemm, cudaFuncAttributeMaxDynamicSharedMemorySize, SMEM1);
    cudaFuncSetAttribute(k3_gat,  cudaFuncAttributeMaxDynamicSharedMemorySize, SMEM3);

    k1h_gemm<<<dim3(4, 48), 256, SMEM1>>>(h, W, a);
    k3_gat<<<48*JSP, 384, SMEM3>>>(adj);
    k4_reduce<<<NN/16, 256>>>(out);
}

// round 16
// speedup vs baseline: 1.1732x; 1.1503x over previous
#include <cuda_runtime.h>
#include <cuda_fp16.h>
#include <cstdint>

#define NN 6144
#define NF 256
#define NH 4
#define ND 64
#define IB 128               // i-rows per CTA (k3)
#define JSP 3                // j splits
#define JL 2048              // j per CTA
#define NC2 32               // chunks of 64

// ---- scratch ----
__device__ __align__(256) __half  g_ht16[NH*NN*ND];   // [h][n][d]
__device__ __align__(256) __half2 g_srcAC2[NH*NN];    // (e^src, e^{0.2src})
__device__ __align__(256) __half2 g_tgtBD2[NH*NN];    // (e^tgt, e^{0.2tgt})
__device__ __align__(256) float   g_num[JSP*NH*NN*ND];
__device__ __align__(256) float   g_den[JSP*NH*NN];

// k3 smem byte offsets
#define POFF(b,h)  (((b)*4+(h))*16384)                 // 128 rows x 128B, swizzled
#define BOFF(b,h)  (131072 + ((b)*4+(h))*8192)         // 64 rows x 128B, swizzled
#define TOFF(s,h)  (196608 + ((s)*4+(h))*256)          // 64 half2
#define SMEM3      200704

__device__ __forceinline__ unsigned smem_u32(const void* p){
    return (unsigned)__cvta_generic_to_shared(p);
}
__device__ __forceinline__ unsigned h2u(__half2 v){ return *reinterpret_cast<unsigned*>(&v); }
__device__ __forceinline__ __half2 u2h(unsigned v){ return *reinterpret_cast<__half2*>(&v); }

// ------------------------------------------------------------------
// k1h: ht = h @ W via fp16 mma (fp32 accum) + fused src/tgt exps.
// grid (4 heads, 96), block 128. 64-row tiles -> 3 CTAs/SM residency.
// ------------------------------------------------------------------
#define HS_ST 264   // halves per row (256+8)
#define WS_ST 72    // halves per row (64+8)
#define SMEM1 ((64*HS_ST + 256*WS_ST)*2)

__global__ void __launch_bounds__(128) k1h_gemm(const float* __restrict__ h,
                                                const float* __restrict__ W,
                                                const float* __restrict__ a) {
    extern __shared__ char smem[];
    __half* Hs = reinterpret_cast<__half*>(smem);            // [64][HS_ST]
    __half* Ws = Hs + 64*HS_ST;                              // [256][WS_ST]
    const int tid = threadIdx.x, w = tid >> 5, lane = tid & 31;
    const int head = blockIdx.x;
    const int n0 = blockIdx.y * 64;

    {   // load h rows (convert fp32->fp16): 128 threads, 64 rows, 2 threads/row
        int row = tid >> 1, ch = (tid & 1) * 128;
        #pragma unroll 8
        for (int q = 0; q < 32; q++){
            float4 v = *reinterpret_cast<const float4*>(&h[(size_t)(n0+row)*NF + ch + q*4]);
            __half2 lo = __floats2half2_rn(v.x, v.y), hi = __floats2half2_rn(v.z, v.w);
            uint2 o; o.x = h2u(lo); o.y = h2u(hi);
            *reinterpret_cast<uint2*>(&Hs[row*HS_ST + ch + q*4]) = o;
        }
    }
    {   // load W column block for this head: 256 k-rows, 2 per thread
        #pragma unroll
        for (int kk = 0; kk < 2; kk++){
            int k = tid + kk*128;
            #pragma unroll 4
            for (int q = 0; q < 16; q++){
                float4 v = *reinterpret_cast<const float4*>(&W[(size_t)k*NF + head*ND + q*4]);
                __half2 lo = __floats2half2_rn(v.x, v.y), hi = __floats2half2_rn(v.z, v.w);
                uint2 o; o.x = h2u(lo); o.y = h2u(hi);
                *reinterpret_cast<uint2*>(&Ws[k*WS_ST + q*4]) = o;
            }
        }
    }
    __syncthreads();

    float acc[8][4] = {};
    #pragma unroll
    for (int ks = 0; ks < 16; ks++){
        uint32_t af[4];
        {
            int r = w*16 + (lane & 15);
            unsigned addr = smem_u32(Hs) + (unsigned)(r*HS_ST*2 + ks*32 + (lane>>4)*16);
            asm volatile("ldmatrix.sync.aligned.m8n8.x4.shared.b16 {%0,%1,%2,%3}, [%4];\n"
                : "=r"(af[0]),"=r"(af[1]),"=r"(af[2]),"=r"(af[3]) : "r"(addr));
        }
        uint32_t bf[8][2];
        #pragma unroll
        for (int nt = 0; nt < 8; nt++){
            int kr = ks*16 + (lane & 15);
            unsigned addr = smem_u32(Ws) + (unsigned)(kr*WS_ST*2 + nt*16);
            asm volatile("ldmatrix.sync.aligned.m8n8.x2.trans.shared.b16 {%0,%1}, [%2];\n"
                : "=r"(bf[nt][0]),"=r"(bf[nt][1]) : "r"(addr));
        }
        #pragma unroll
        for (int nt = 0; nt < 8; nt++)
            asm volatile(
              "mma.sync.aligned.m16n8k16.row.col.f32.f16.f16.f32 "
              "{%0,%1,%2,%3}, {%4,%5,%6,%7}, {%8,%9}, {%0,%1,%2,%3};\n"
              : "+f"(acc[nt][0]),"+f"(acc[nt][1]),"+f"(acc[nt][2]),"+f"(acc[nt][3])
              : "r"(af[0]),"r"(af[1]),"r"(af[2]),"r"(af[3]),
                "r"(bf[nt][0]),"r"(bf[nt][1]));
    }

    int r0 = n0 + w*16 + (lane >> 2);
    #pragma unroll
    for (int nt = 0; nt < 8; nt++){
        int d = nt*8 + (lane & 3)*2;
        *reinterpret_cast<__half2*>(&g_ht16[((size_t)head*NN + r0)*ND + d])
            = __floats2half2_rn(acc[nt][0], acc[nt][1]);
        *reinterpret_cast<__half2*>(&g_ht16[((size_t)head*NN + r0 + 8)*ND + d])
            = __floats2half2_rn(acc[nt][2], acc[nt][3]);
    }

    // ---- fused src/tgt logits (fp32) ----
    float s0=0.f, s1=0.f, t0=0.f, t1=0.f;
    #pragma unroll
    for (int nt = 0; nt < 8; nt++){
        int d = nt*8 + (lane & 3)*2;
        float2 av = *reinterpret_cast<const float2*>(&a[head*2*ND + d]);
        float2 bv = *reinterpret_cast<const float2*>(&a[head*2*ND + ND + d]);
        s0 += acc[nt][0]*av.x + acc[nt][1]*av.y;
        t0 += acc[nt][0]*bv.x + acc[nt][1]*bv.y;
        s1 += acc[nt][2]*av.x + acc[nt][3]*av.y;
        t1 += acc[nt][2]*bv.x + acc[nt][3]*bv.y;
    }
    #pragma unroll
    for (int off = 1; off <= 2; off <<= 1){
        s0 += __shfl_xor_sync(0xffffffffu, s0, off);
        s1 += __shfl_xor_sync(0xffffffffu, s1, off);
        t0 += __shfl_xor_sync(0xffffffffu, t0, off);
        t1 += __shfl_xor_sync(0xffffffffu, t1, off);
    }
    if ((lane & 3) == 0){
        g_srcAC2[head*NN + r0]     = __floats2half2_rn(expf(s0), expf(0.2f*s0));
        g_srcAC2[head*NN + r0 + 8] = __floats2half2_rn(expf(s1), expf(0.2f*s1));
        g_tgtBD2[head*NN + r0]     = __floats2half2_rn(expf(t0), expf(0.2f*t0));
        g_tgtBD2[head*NN + r0 + 8] = __floats2half2_rn(expf(t1), expf(0.2f*t1));
    }
}

// ------------------------------------------------------------------
// k3: flash GAT (R8 structure — best measured). 144 CTAs, 256 thr / 8 warps.
// warp w: head = w&3, m-half = w>>2. Per chunk: mma first, then next pgen.
// ------------------------------------------------------------------
__global__ void __launch_bounds__(256, 1) k3_gat(const int* __restrict__ adj){
    extern __shared__ char smem[];
    const unsigned sbase = smem_u32(smem);
    const int tid = threadIdx.x, w = tid >> 5, lane = tid & 31;
    const int h = w & 3, mh = w >> 2;
    const int ib = blockIdx.x / 3, split = blockIdx.x % 3;
    const int i0 = ib * IB, j0 = split * JL;
    const int rg = tid >> 2, jg = tid & 3;    // rows 2rg,2rg+1 ; j block jg*16

    __half2 AC[2][NH];
    #pragma unroll
    for (int rr = 0; rr < 2; rr++)
        #pragma unroll
        for (int hh = 0; hh < NH; hh++)
            AC[rr][hh] = g_srcAC2[hh*NN + i0 + 2*rg + rr];

    float den[2][NH] = {};
    float acc[4][8][4] = {};     // [mt][nt][frag]

    auto loadB = [&](int buf, int c){
        #pragma unroll
        for (int t = 0; t < 8; t++){
            int idx = tid + t*256;
            int hh = idx >> 9, rw = (idx >> 3) & 63, s = idx & 7;
            const __half* src = &g_ht16[((size_t)hh*NN + j0 + c*64 + rw)*ND + s*8];
            unsigned dst = sbase + BOFF(buf,hh) + rw*128 + ((s*16) ^ ((rw&7)<<4));
            asm volatile("cp.async.cg.shared.global [%0], [%1], 16;\n" :: "r"(dst), "l"(src));
        }
    };
    auto loadTgt = [&](int slot, int c){
        if (tid < 64){
            int hh = tid >> 4, q = tid & 15;
            const __half2* src = g_tgtBD2 + hh*NN + j0 + c*64 + q*4;
            unsigned dst = sbase + TOFF(slot,hh) + q*16;
            asm volatile("cp.async.cg.shared.global [%0], [%1], 16;\n" :: "r"(dst), "l"(src));
        }
    };
    auto loadAdj = [&](int4* dst, int cc){
        #pragma unroll
        for (int rr = 0; rr < 2; rr++){
            const int4* base = reinterpret_cast<const int4*>(
                adj + (size_t)(i0 + 2*rg + rr)*NN + j0 + cc*64 + jg*16);
            #pragma unroll
            for (int q = 0; q < 4; q++) dst[rr*4+q] = __ldcs(base + q);
        }
    };

    auto pgen = [&](int buf, int slot, const int4* adjr){
        unsigned mk[2][8];
        #pragma unroll
        for (int rr = 0; rr < 2; rr++)
            #pragma unroll
            for (int p = 0; p < 8; p++){
                int4 aq = adjr[rr*4 + (p>>1)];
                int a0 = (p&1) ? aq.z : aq.x;
                int a1 = (p&1) ? aq.w : aq.y;
                mk[rr][p] = (unsigned)a0*0x3C00u + (unsigned)a1*0x3C000000u;
            }
        #pragma unroll
        for (int hh = 0; hh < NH; hh++){
            const uint4* tp = reinterpret_cast<const uint4*>(smem + TOFF(slot,hh) + jg*64);
            uint4 T0 = tp[0], T1 = tp[1], T2 = tp[2], T3 = tp[3];
            unsigned tv[16] = {T0.x,T0.y,T0.z,T0.w, T1.x,T1.y,T1.z,T1.w,
                               T2.x,T2.y,T2.z,T2.w, T3.x,T3.y,T3.z,T3.w};
            #pragma unroll
            for (int rr = 0; rr < 2; rr++){
                const int r = 2*rg + rr;
                __half2 ac = AC[rr][hh];
                unsigned o[8];
                float dsum = 0.f;
                #pragma unroll
                for (int p = 0; p < 8; p++){
                    __half2 t0 = __hmul2(ac, u2h(tv[2*p]));
                    __half2 t1 = __hmul2(ac, u2h(tv[2*p+1]));
                    __half p0 = __hmax(__low2half(t0), __high2half(t0));
                    __half p1 = __hmax(__low2half(t1), __high2half(t1));
                    __half2 pm = __hmul2(__halves2half2(p0, p1), u2h(mk[rr][p]));
                    o[p] = h2u(pm);
                    float2 f = __half22float2(pm);
                    dsum += f.x + f.y;
                }
                den[rr][hh] += dsum;
                unsigned sw = (unsigned)((r&7)<<4);
                char* pb = smem + POFF(buf,hh) + r*128;
                uint4 o0; o0.x=o[0]; o0.y=o[1]; o0.z=o[2]; o0.w=o[3];
                uint4 o1; o1.x=o[4]; o1.y=o[5]; o1.z=o[6]; o1.w=o[7];
                *reinterpret_cast<uint4*>(pb + (((unsigned)(jg*32))      ^ sw)) = o0;
                *reinterpret_cast<uint4*>(pb + (((unsigned)(jg*32 + 16)) ^ sw)) = o1;
            }
        }
    };

    auto do_mma = [&](int buf){
        const unsigned PB = sbase + POFF(buf,h);
        const unsigned BB = sbase + BOFF(buf,h);
        #pragma unroll
        for (int ks = 0; ks < 4; ks++){
            uint32_t af[4][4];
            #pragma unroll
            for (int mt = 0; mt < 4; mt++){
                int r = mh*64 + mt*16 + (lane & 15);
                unsigned cb = (unsigned)(ks*32 + (lane>>4)*16);
                unsigned addr = PB + r*128 + (cb ^ ((r&7)<<4));
                asm volatile("ldmatrix.sync.aligned.m8n8.x4.shared.b16 {%0,%1,%2,%3}, [%4];\n"
                    : "=r"(af[mt][0]),"=r"(af[mt][1]),"=r"(af[mt][2]),"=r"(af[mt][3])
                    : "r"(addr));
            }
            uint32_t bf[8][2];
            #pragma unroll
            for (int nt = 0; nt < 8; nt++){
                int jr = ks*16 + (lane & 15);
                unsigned addr = BB + jr*128 + (((unsigned)(nt*16)) ^ ((jr&7)<<4));
                asm volatile("ldmatrix.sync.aligned.m8n8.x2.trans.shared.b16 {%0,%1}, [%2];\n"
                    : "=r"(bf[nt][0]),"=r"(bf[nt][1]) : "r"(addr));
            }
            #pragma unroll
            for (int mt = 0; mt < 4; mt++)
                #pragma unroll
                for (int nt = 0; nt < 8; nt++)
                    asm volatile(
                      "mma.sync.aligned.m16n8k16.row.col.f32.f16.f16.f32 "
                      "{%0,%1,%2,%3}, {%4,%5,%6,%7}, {%8,%9}, {%0,%1,%2,%3};\n"
                      : "+f"(acc[mt][nt][0]),"+f"(acc[mt][nt][1]),
                        "+f"(acc[mt][nt][2]),"+f"(acc[mt][nt][3])
                      : "r"(af[mt][0]),"r"(af[mt][1]),"r"(af[mt][2]),"r"(af[mt][3]),
                        "r"(bf[nt][0]),"r"(bf[nt][1]));
        }
    };

    // ---- prologue ----
    int4 adjr[8];
    loadTgt(0, 0); loadTgt(1, 1); loadB(0, 0);
    asm volatile("cp.async.commit_group;\n" ::: "memory");
    loadAdj(adjr, 0);
    asm volatile("cp.async.wait_group 0;\n" ::: "memory");
    __syncthreads();
    pgen(0, 0, adjr);                       // P(0)

    // ---- main loop ----
    for (int c = 0; c < NC2; ++c){
        const int buf = c & 1;
        asm volatile("cp.async.wait_group 0;\n" ::: "memory");  // B(c), tgt(c+1) landed
        __syncthreads();                                        // + P(c) visible
        if (c + 1 < NC2) loadB(buf ^ 1, c + 1);
        if (c + 2 < NC2) loadTgt((c + 2) & 3, c + 2);
        asm volatile("cp.async.commit_group;\n" ::: "memory");
        if (c + 1 < NC2) loadAdj(adjr, c + 1);   // lands under mma
        do_mma(buf);                              // tensor pipe first
        if (c + 1 < NC2) pgen(buf ^ 1, (c + 1) & 3, adjr);
    }

    // ---- epilogue: den lane-reduce + partial writes ----
    #pragma unroll
    for (int rr = 0; rr < 2; rr++)
        #pragma unroll
        for (int hh = 0; hh < NH; hh++){
            float v = den[rr][hh];
            v += __shfl_xor_sync(0xffffffffu, v, 1);
            v += __shfl_xor_sync(0xffffffffu, v, 2);
            if (jg == 0)
                g_den[((size_t)split*NH + hh)*NN + i0 + 2*rg + rr] = v;
        }
    #pragma unroll
    for (int mt = 0; mt < 4; mt++){
        int r0 = i0 + mh*64 + mt*16 + (lane >> 2);
        #pragma unroll
        for (int nt = 0; nt < 8; nt++){
            int d = nt*8 + (lane & 3)*2;
            float2 v0; v0.x = acc[mt][nt][0]; v0.y = acc[mt][nt][1];
            float2 v1; v1.x = acc[mt][nt][2]; v1.y = acc[mt][nt][3];
            *reinterpret_cast<float2*>(&g_num[(((size_t)split*NH + h)*NN + r0)*ND + d]) = v0;
            *reinterpret_cast<float2*>(&g_num[(((size_t)split*NH + h)*NN + r0 + 8)*ND + d]) = v1;
        }
    }
}

// ------------------------------------------------------------------
// k4: combine split partials, divide, mean over heads.
// grid NN/16, block 256: 16 rows/CTA, 16 threads x float4 per row.
// ------------------------------------------------------------------
__global__ void __launch_bounds__(256) k4_reduce(float* __restrict__ out){
    const int tid = threadIdx.x;
    const int i  = blockIdx.x * 16 + (tid >> 4);
    const int d4 = (tid & 15) * 4;
    __shared__ float rinv[16][NH];
    if (tid < 64){
        int row = blockIdx.x * 16 + (tid >> 2), hh = tid & 3;
        float s = 0.f;
        #pragma unroll
        for (int sp = 0; sp < JSP; sp++) s += g_den[((size_t)sp*NH + hh)*NN + row];
        rinv[tid >> 2][hh] = 1.f / s;
    }
    __syncthreads();
    float4 accv = make_float4(0.f, 0.f, 0.f, 0.f);
    #pragma unroll
    for (int hh = 0; hh < NH; hh++){
        float4 s = make_float4(0.f, 0.f, 0.f, 0.f);
        #pragma unroll
        for (int sp = 0; sp < JSP; sp++){
            float4 v = *reinterpret_cast<const float4*>(
                &g_num[(((size_t)sp*NH + hh)*NN + i)*ND + d4]);
            s.x += v.x; s.y += v.y; s.z += v.z; s.w += v.w;
        }
        float r = rinv[tid >> 4][hh];
        accv.x += s.x*r; accv.y += s.y*r; accv.z += s.z*r; accv.w += s.w*r;
    }
    accv.x *= 0.25f; accv.y *= 0.25f; accv.z *= 0.25f; accv.w *= 0.25f;
    *reinterpret_cast<float4*>(&out[(size_t)i*ND + d4]) = accv;
}

// ------------------------------------------------------------------
extern "C" void kernel_launch(void* const* d_in, const int* in_sizes, int n_in,
                              void* d_out, int out_size) {
    const float* h   = (const float*)d_in[0];
    const int*   adj = (const int*)d_in[1];
    const float* W   = (const float*)d_in[2];
    const float* a   = (const float*)d_in[3];
    float* out = (float*)d_out;

    cudaFuncSetAttribute(k1h_gemm, cudaFuncAttributeMaxDynamicSharedMemorySize, SMEM1);
    cudaFuncSetAttribute(k3_gat,  cudaFuncAttributeMaxDynamicSharedMemorySize, SMEM3);

    k1h_gemm<<<dim3(4, 96), 128, SMEM1>>>(h, W, a);
    k3_gat<<<48*JSP, 256, SMEM3>>>(adj);
    k4_reduce<<<NN/16, 256>>>(out);
}